// round 14
// baseline (speedup 1.0000x reference)
#include <cuda_runtime.h>
#include <cuda_bf16.h>
#include <math.h>
#include <stdint.h>

#define NTOK 4096
#define NELEM (NTOK*96)
#define SCALE_F 0.35355339059327373f
#define NEG_INF (-3.402823466e38f)

__device__ float g_qkv[9][2][8*NTOK];
__device__ float g_ycam[2][8*NTOK];
__device__ float g_ypam[2][8*NTOK];
__device__ float g_ycham[2][8*NTOK];
__device__ float g_ycwam[2][NELEM];
// split-K3 partials for cwam
__device__ float g_pl[3][2][6144];
__device__ float g_pY[3][2][6144][64];
// prepacked bf16 hi/lo K + Vt tiles, exact smem image per 128-token tile
__device__ uint32_t g_kv[2][48][18560];

struct QKVParams { const float* w[9]; const float* bia[9]; };
struct EpiParams { const float* pw[4]; const float* g[4]; const float* gamma[4]; };

// ---- fast exp on the FMA pipe (no MUFU) ----
__device__ __forceinline__ float fexp(float x) {
    x = fmaxf(x, -80.f);
    float t = fmaf(x, 1.4426950408889634f, 12582912.f);
    float e = t - 12582912.f;
    float f = fmaf(x, 1.4426950408889634f, -e);
    float p = 1.5403530e-4f;
    p = fmaf(p, f, 1.3333558e-3f);
    p = fmaf(p, f, 9.6181291e-3f);
    p = fmaf(p, f, 5.5504109e-2f);
    p = fmaf(p, f, 2.4022651e-1f);
    p = fmaf(p, f, 6.9314718e-1f);
    p = fmaf(p, f, 1.0f);
    return p * __int_as_float(((int)e + 127) << 23);
}

// ---- cheap bf16 hi/lo split ----
__device__ __forceinline__ float trunchi(float a) {
    return __int_as_float(__float_as_int(a) & 0xffff0000u);
}
__device__ __forceinline__ uint32_t prmthi(float a, float b) {
    uint32_t r;
    asm("prmt.b32 %0, %1, %2, 0x7632;" : "=r"(r) : "r"(__float_as_int(a)), "r"(__float_as_int(b)));
    return r;
}
__device__ __forceinline__ uint32_t cvt2(float lo, float hi) {
    uint32_t r;
    asm("cvt.rn.bf16x2.f32 %0, %1, %2;" : "=r"(r) : "f"(hi), "f"(lo));
    return r;
}

#define MMA16(d, a, b0, b1) asm volatile( \
    "mma.sync.aligned.m16n8k16.row.col.f32.bf16.bf16.f32 " \
    "{%0,%1,%2,%3},{%4,%5,%6,%7},{%8,%9},{%0,%1,%2,%3};" \
    : "+f"((d)[0]),"+f"((d)[1]),"+f"((d)[2]),"+f"((d)[3]) \
    : "r"((a)[0]),"r"((a)[1]),"r"((a)[2]),"r"((a)[3]), "r"(b0),"r"(b1))

// smem layout in u32 units (identical to gmem packed tile image)
#define KHI_O   0            /* 128 tok * 36 u32 */
#define KLO_O   4608
#define VTH_O   9216         /* 64 tokpair * 73 u32 (padded) */
#define VTL_O   13888
#define TILE_U32 18560
#define CWAM_SMEM (TILE_U32*4)  /* 74240 B */

// ======== conv_kv: build packed bf16 tile images once (grid 48 x 2) ========
__global__ void __launch_bounds__(128) conv_kv(const float* __restrict__ x) {
    extern __shared__ uint32_t sm[];
    uint32_t* khi = sm + KHI_O;
    uint32_t* klo = sm + KLO_O;
    uint32_t* vth = sm + VTH_O;
    uint32_t* vtl = sm + VTL_O;
    const int tile = blockIdx.x, b = blockIdx.y, t = threadIdx.x;
    const float* xb = x + b*NELEM;
    const int c0 = tile*128;
#pragma unroll
    for (int i = 0; i < 8; i++) {
        int j = i*128 + t;
        int tp = j >> 4, dq = j & 15;
        float4 a4 = __ldg((const float4*)(xb + (c0 + 2*tp)*64) + dq);
        float4 b4 = __ldg((const float4*)(xb + (c0 + 2*tp + 1)*64) + dq);
        float rax = a4.x - trunchi(a4.x), ray = a4.y - trunchi(a4.y);
        float raz = a4.z - trunchi(a4.z), raw = a4.w - trunchi(a4.w);
        float rbx = b4.x - trunchi(b4.x), rby = b4.y - trunchi(b4.y);
        float rbz = b4.z - trunchi(b4.z), rbw = b4.w - trunchi(b4.w);
        int ke = (2*tp)*36 + dq*2, ko = ke + 36;
        khi[ke  ] = prmthi(a4.x, a4.y);  khi[ke+1] = prmthi(a4.z, a4.w);
        khi[ko  ] = prmthi(b4.x, b4.y);  khi[ko+1] = prmthi(b4.z, b4.w);
        klo[ke  ] = cvt2(rax, ray);      klo[ke+1] = cvt2(raz, raw);
        klo[ko  ] = cvt2(rbx, rby);      klo[ko+1] = cvt2(rbz, rbw);
        int vb = tp*73 + dq*4;
        vth[vb  ] = prmthi(a4.x, b4.x);
        vth[vb+1] = prmthi(a4.y, b4.y);
        vth[vb+2] = prmthi(a4.z, b4.z);
        vth[vb+3] = prmthi(a4.w, b4.w);
        vtl[vb  ] = cvt2(rax, rbx);
        vtl[vb+1] = cvt2(ray, rby);
        vtl[vb+2] = cvt2(raz, rbz);
        vtl[vb+3] = cvt2(raw, rbw);
    }
    __syncthreads();
    uint4* dst = (uint4*)g_kv[b][tile];
    const uint4* src = (const uint4*)sm;
    for (int i = t; i < TILE_U32/4; i += 128) dst[i] = src[i];
}

// ======== CWAM split-K3 flash (no-max softmax), prepacked tiles ========
__global__ void __launch_bounds__(128) cwam_mma(const float* __restrict__ x) {
    extern __shared__ uint32_t sm[];
    uint32_t* khi = sm + KHI_O;
    uint32_t* klo = sm + KLO_O;
    uint32_t* vth = sm + VTH_O;
    uint32_t* vtl = sm + VTL_O;
    const int b = blockIdx.y, z = blockIdx.z, a0 = blockIdx.x*64, t = threadIdx.x;
    const int w = t >> 5, lane = t & 31, g = lane >> 2, q = lane & 3;
    const float* xb = x + b*NELEM;
    uint32_t qhi[4][4], qlo[4][4];
    const int r0 = a0 + w*16 + g;
#pragma unroll
    for (int ks = 0; ks < 4; ks++)
#pragma unroll
        for (int half = 0; half < 2; half++)
#pragma unroll
            for (int rr = 0; rr < 2; rr++) {
                int row = r0 + rr*8;
                int col = ks*16 + half*8 + 2*q;
                float2 v = *(const float2*)(xb + row*64 + col);
                v.x *= SCALE_F; v.y *= SCALE_F;
                qhi[ks][half*2+rr] = prmthi(v.x, v.y);
                qlo[ks][half*2+rr] = cvt2(v.x - trunchi(v.x), v.y - trunchi(v.y));
            }
    float l0 = 0.f, l1 = 0.f;
    float Y[8][4];
#pragma unroll
    for (int i = 0; i < 8; i++) { Y[i][0]=0.f; Y[i][1]=0.f; Y[i][2]=0.f; Y[i][3]=0.f; }

    const int tbeg = z*16, tend = tbeg + 16;
    for (int tile = tbeg; tile < tend; tile++) {
        __syncthreads();
        {   // dumb coalesced copy of the prepacked tile image
            const uint4* src = (const uint4*)g_kv[b][tile];
            uint4* dst = (uint4*)sm;
#pragma unroll
            for (int i = 0; i < 36; i++) dst[i*128 + t] = src[i*128 + t];
            if (t < TILE_U32/4 - 36*128) dst[36*128 + t] = src[36*128 + t];
        }
        __syncthreads();
        float d[16][4];
#pragma unroll
        for (int ns = 0; ns < 16; ns++) { d[ns][0]=0.f; d[ns][1]=0.f; d[ns][2]=0.f; d[ns][3]=0.f; }
#pragma unroll
        for (int ks = 0; ks < 4; ks++)
#pragma unroll
            for (int ns = 0; ns < 16; ns++) {
                int tok = ns*8 + g;
                uint32_t bh0 = khi[tok*36 + ks*8 + q];
                uint32_t bh1 = khi[tok*36 + ks*8 + 4 + q];
                uint32_t bl0 = klo[tok*36 + ks*8 + q];
                uint32_t bl1 = klo[tok*36 + ks*8 + 4 + q];
                MMA16(d[ns], qhi[ks], bh0, bh1);
                MMA16(d[ns], qhi[ks], bl0, bl1);
                MMA16(d[ns], qlo[ks], bh0, bh1);
            }
#pragma unroll
        for (int ns = 0; ns < 16; ns++) {
            d[ns][0] = fexp(d[ns][0]); d[ns][1] = fexp(d[ns][1]);
            d[ns][2] = fexp(d[ns][2]); d[ns][3] = fexp(d[ns][3]);
            l0 += d[ns][0] + d[ns][1];
            l1 += d[ns][2] + d[ns][3];
        }
#pragma unroll
        for (int ks2 = 0; ks2 < 8; ks2++) {
            uint32_t ah[4], al[4];
            float p00 = d[2*ks2][0],   p01 = d[2*ks2][1];
            float p02 = d[2*ks2][2],   p03 = d[2*ks2][3];
            float p10 = d[2*ks2+1][0], p11 = d[2*ks2+1][1];
            float p12 = d[2*ks2+1][2], p13 = d[2*ks2+1][3];
            ah[0] = prmthi(p00, p01);  al[0] = cvt2(p00 - trunchi(p00), p01 - trunchi(p01));
            ah[1] = prmthi(p02, p03);  al[1] = cvt2(p02 - trunchi(p02), p03 - trunchi(p03));
            ah[2] = prmthi(p10, p11);  al[2] = cvt2(p10 - trunchi(p10), p11 - trunchi(p11));
            ah[3] = prmthi(p12, p13);  al[3] = cvt2(p12 - trunchi(p12), p13 - trunchi(p13));
#pragma unroll
            for (int nd = 0; nd < 8; nd++) {
                int dim = nd*8 + g;
                uint32_t bh0 = vth[(ks2*8 + q)*73 + dim];
                uint32_t bh1 = vth[(ks2*8 + 4 + q)*73 + dim];
                uint32_t bl0 = vtl[(ks2*8 + q)*73 + dim];
                uint32_t bl1 = vtl[(ks2*8 + 4 + q)*73 + dim];
                MMA16(Y[nd], ah, bh0, bh1);
                MMA16(Y[nd], al, bh0, bh1);
                MMA16(Y[nd], ah, bl0, bl1);
            }
        }
    }
#pragma unroll
    for (int off = 1; off <= 2; off <<= 1) {
        l0 += __shfl_xor_sync(0xffffffffu, l0, off);
        l1 += __shfl_xor_sync(0xffffffffu, l1, off);
    }
    float (*pY)[64] = g_pY[z][b];
#pragma unroll
    for (int nd = 0; nd < 8; nd++) {
        int col = nd*8 + 2*q;
        *(float2*)(&pY[r0][col])     = make_float2(Y[nd][0], Y[nd][1]);
        *(float2*)(&pY[r0 + 8][col]) = make_float2(Y[nd][2], Y[nd][3]);
    }
    if (q == 0) {
        g_pl[z][b][r0]   = l0;
        g_pl[z][b][r0+8] = l1;
    }
}

// merge: Y = sum(Yz) / sum(lz)
__global__ void __launch_bounds__(256) cwam_merge() {
    const int b = blockIdx.y;
    const int row = blockIdx.x*4 + (threadIdx.x >> 6);
    const int d = threadIdx.x & 63;
    float l = g_pl[0][b][row] + g_pl[1][b][row] + g_pl[2][b][row];
    float y = g_pY[0][b][row][d] + g_pY[1][b][row][d] + g_pY[2][b][row][d];
    g_ycwam[b][row*64 + d] = y / l;
}

// ======== fused qkv conv1x1 ========
__global__ void __launch_bounds__(256) qkv_kernel(const float* __restrict__ x, QKVParams P) {
    __shared__ float sw[72*100];
    __shared__ float sb[72];
    const int b = blockIdx.y, n0 = blockIdx.x*128, t = threadIdx.x;
    for (int i = t; i < 72*96; i += 256) {
        int o = i/96, c = i - o*96;
        sw[o*100+c] = __ldg(P.w[o%9] + (o/9)*96 + c);
    }
    if (t < 72) sb[t] = __ldg(P.bia[t%9] + t/9);
    __syncthreads();
    const int og = t & 7, nl = t >> 3;
    const float* xb = x + b*NELEM + n0 + nl;
    float acc[9][4];
#pragma unroll
    for (int kk = 0; kk < 9; kk++) {
        float bb = sb[og*9+kk];
#pragma unroll
        for (int j = 0; j < 4; j++) acc[kk][j] = bb;
    }
    for (int c = 0; c < 96; c++) {
        float xv[4];
#pragma unroll
        for (int j = 0; j < 4; j++) xv[j] = __ldg(xb + c*NTOK + 32*j);
#pragma unroll
        for (int kk = 0; kk < 9; kk++) {
            float wv = sw[(og*9+kk)*100 + c];
#pragma unroll
            for (int j = 0; j < 4; j++) acc[kk][j] += wv*xv[j];
        }
    }
#pragma unroll
    for (int kk = 0; kk < 9; kk++)
#pragma unroll
        for (int j = 0; j < 4; j++)
            g_qkv[kk][b][og*NTOK + n0 + nl + 32*j] = acc[kk][j];
}

// ======== CAM ========
__global__ void __launch_bounds__(256) cam_kernel() {
    const int b = blockIdx.x, slice = blockIdx.y;
    const float *q = g_qkv[0][b], *k = g_qkv[1][b], *v = g_qkv[2][b];
    __shared__ float sp[8][8];
    const int w = threadIdx.x >> 5, lane = threadIdx.x & 31;
    float acc[8] = {};
    for (int i = lane; i < NTOK; i += 32) {
        float qv = q[w*NTOK+i];
#pragma unroll
        for (int d = 0; d < 8; d++) acc[d] += qv*k[d*NTOK+i];
    }
#pragma unroll
    for (int d = 0; d < 8; d++)
#pragma unroll
        for (int off = 16; off; off >>= 1)
            acc[d] += __shfl_xor_sync(0xffffffffu, acc[d], off);
    if (lane == 0) {
        float mx = NEG_INF, s = 0.f, e[8];
#pragma unroll
        for (int d = 0; d < 8; d++) mx = fmaxf(mx, acc[d]*SCALE_F);
#pragma unroll
        for (int d = 0; d < 8; d++) { e[d] = fexp(acc[d]*SCALE_F - mx); s += e[d]; }
#pragma unroll
        for (int d = 0; d < 8; d++) sp[w][d] = e[d]/s;
    }
    __syncthreads();
    for (int idx = threadIdx.x; idx < 4096; idx += 256) {
        int c = idx >> 9, n = slice*512 + (idx & 511);
        float a0 = 0.f;
#pragma unroll
        for (int d = 0; d < 8; d++) a0 += sp[c][d]*v[d*NTOK+n];
        g_ycam[b][c*NTOK+n] = a0;
    }
}

// ======== PAM v3: flash w/ fixed max, 32 rows/CTA, 8-way m-split ========
__global__ void __launch_bounds__(256) pam_kernel() {
    const int a0 = blockIdx.x*32, b = blockIdx.y;
    const float *q = g_qkv[3][b], *k = g_qkv[4][b], *v = g_qkv[5][b];
    __shared__ float kt[512][8], vt[512][8];
    const int a = threadIdx.x >> 3, p = threadIdx.x & 7;
    float qr[8];
#pragma unroll
    for (int c = 0; c < 8; c++) qr[c] = q[c*NTOK + a0 + a]*SCALE_F;
    float l = 0.f, y[8] = {};
    for (int m0 = 0; m0 < NTOK; m0 += 512) {
        __syncthreads();
        for (int i = threadIdx.x; i < 4096; i += 256) {
            int c = i >> 9, mm = i & 511;
            kt[mm][c] = k[c*NTOK + m0 + mm];
            vt[mm][c] = v[c*NTOK + m0 + mm];
        }
        __syncthreads();
        for (int mi = p; mi < 512; mi += 8) {
            float4 k0 = *(const float4*)&kt[mi][0], k1 = *(const float4*)&kt[mi][4];
            float s = qr[0]*k0.x+qr[1]*k0.y+qr[2]*k0.z+qr[3]*k0.w
                    + qr[4]*k1.x+qr[5]*k1.y+qr[6]*k1.z+qr[7]*k1.w;
            float pe = fexp(s);
            l += pe;
            float4 v0 = *(const float4*)&vt[mi][0], v1 = *(const float4*)&vt[mi][4];
            y[0]+=pe*v0.x; y[1]+=pe*v0.y; y[2]+=pe*v0.z; y[3]+=pe*v0.w;
            y[4]+=pe*v1.x; y[5]+=pe*v1.y; y[6]+=pe*v1.z; y[7]+=pe*v1.w;
        }
    }
#pragma unroll
    for (int off = 1; off <= 4; off <<= 1) {
        l += __shfl_xor_sync(0xffffffffu, l, off);
#pragma unroll
        for (int c = 0; c < 8; c++) y[c] += __shfl_xor_sync(0xffffffffu, y[c], off);
    }
    if (p == 0) {
        float inv = 1.f/l;
#pragma unroll
        for (int c = 0; c < 8; c++) g_ypam[b][(a0+a)*8 + c] = y[c]*inv;
    }
}

// ======== CHAM v3: 512x512, d=64; 8 rows/CTA, smem-staged tiles ========
__global__ void __launch_bounds__(256) cham_kernel() {
    const int a0 = blockIdx.x*8, b = blockIdx.y;
    const float *q = g_qkv[6][b], *k = g_qkv[7][b], *v = g_qkv[8][b];
    __shared__ float sq[8][68];
    __shared__ float kt[64][68];
    __shared__ float ss[8][520];
    const int t = threadIdx.x, r = t >> 5, ln = t & 31;
    for (int i = t; i < 512; i += 256)
        sq[i>>6][i&63] = q[(a0 + (i>>6))*64 + (i&63)] * SCALE_F;
    for (int ch = 0; ch < 8; ch++) {
        __syncthreads();
        for (int i = 0; i < 16; i++) {
            int idx = i*256 + t;
            kt[idx>>6][idx&63] = __ldg(k + ch*4096 + idx);
        }
        __syncthreads();
        float s0 = 0.f, s1 = 0.f;
#pragma unroll
        for (int i = 0; i < 16; i++) {
            float4 qv = *(const float4*)&sq[r][i*4];
            float4 k0 = *(const float4*)&kt[ln][i*4];
            float4 k1 = *(const float4*)&kt[ln+32][i*4];
            s0 += qv.x*k0.x + qv.y*k0.y + qv.z*k0.z + qv.w*k0.w;
            s1 += qv.x*k1.x + qv.y*k1.y + qv.z*k1.z + qv.w*k1.w;
        }
        ss[r][ch*64 + ln]      = s0;
        ss[r][ch*64 + ln + 32] = s1;
    }
    __syncthreads();
    float vals[16], M = NEG_INF;
#pragma unroll
    for (int j = 0; j < 16; j++) { vals[j] = ss[r][ln + 32*j]; M = fmaxf(M, vals[j]); }
#pragma unroll
    for (int off = 16; off; off >>= 1) M = fmaxf(M, __shfl_xor_sync(0xffffffffu, M, off));
    float S = 0.f;
#pragma unroll
    for (int j = 0; j < 16; j++) { vals[j] = fexp(vals[j] - M); S += vals[j]; }
#pragma unroll
    for (int off = 16; off; off >>= 1) S += __shfl_xor_sync(0xffffffffu, S, off);
    float inv = 1.f / S;
#pragma unroll
    for (int j = 0; j < 16; j++) ss[r][ln + 32*j] = vals[j] * inv;
    float y0 = 0.f, y1 = 0.f;
    for (int ch = 0; ch < 8; ch++) {
        __syncthreads();
        for (int i = 0; i < 16; i++) {
            int idx = i*256 + t;
            kt[idx>>6][idx&63] = __ldg(v + ch*4096 + idx);
        }
        __syncthreads();
#pragma unroll 8
        for (int c = 0; c < 64; c++) {
            float pv = ss[r][ch*64 + c];
            y0 += pv * kt[c][ln];
            y1 += pv * kt[c][ln+32];
        }
    }
    g_ycham[b][(a0+r)*64 + ln]      = y0;
    g_ycham[b][(a0+r)*64 + ln + 32] = y1;
}

// ======== epilogue ========
__global__ void __launch_bounds__(256) epi_kernel(float* __restrict__ out, EpiParams E) {
    const int b = blockIdx.y, o = blockIdx.x;
    __shared__ float w[4][9];
    __shared__ float gg[4];
    if (threadIdx.x < 36)
        w[threadIdx.x/9][threadIdx.x%9] = __ldg(E.pw[threadIdx.x/9] + o*9 + threadIdx.x%9);
    if (threadIdx.x < 4)
        gg[threadIdx.x] = __ldg(E.gamma[threadIdx.x]) * (1.f + __ldg(E.g[threadIdx.x]));
    __syncthreads();
    const int g8 = o/12;
    const float* inp[4] = { g_ycam[b] + g8*4096, g_ypam[b] + g8*4096,
                            g_ycham[b] + g8*4096, g_ycwam[b] + o*4096 };
    for (int pix = threadIdx.x; pix < 4096; pix += 256) {
        int h = pix >> 6, wx = pix & 63;
        float acc = 0.f;
#pragma unroll
        for (int br = 0; br < 4; br++) {
            float c = 0.f;
#pragma unroll
            for (int dy = -1; dy <= 1; dy++)
#pragma unroll
                for (int dx = -1; dx <= 1; dx++) {
                    int hh2 = h + dy, ww = wx + dx;
                    float vv = (hh2 >= 0 && hh2 < 64 && ww >= 0 && ww < 64)
                               ? __ldg(inp[br] + hh2*64 + ww) : 0.f;
                    c += w[br][(dy+1)*3 + dx + 1] * vv;
                }
            float ge = 0.5f*c*(1.f + erff(c*0.70710678118654752f));
            acc += gg[br]*ge;
        }
        out[b*NELEM + pix*96 + o] = acc;
    }
}

extern "C" void kernel_launch(void* const* d_in, const int* in_sizes, int n_in,
                              void* d_out, int out_size) {
    const float* x = (const float*)d_in[0];
    static const int wi[9] = {1,3,5, 9,11,13, 17,19,21};
    QKVParams P;
    for (int i = 0; i < 9; i++) {
        P.w[i]   = (const float*)d_in[wi[i]];
        P.bia[i] = (const float*)d_in[wi[i]+1];
    }
    static const int pi[4] = {7,15,23,25};
    EpiParams E;
    for (int i = 0; i < 4; i++) {
        E.pw[i]    = (const float*)d_in[pi[i]];
        E.g[i]     = (const float*)d_in[pi[i]+1];
        E.gamma[i] = (const float*)d_in[27+i];
    }
    float* out = (float*)d_out;
    cudaFuncSetAttribute(conv_kv,  cudaFuncAttributeMaxDynamicSharedMemorySize, CWAM_SMEM);
    cudaFuncSetAttribute(cwam_mma, cudaFuncAttributeMaxDynamicSharedMemorySize, CWAM_SMEM);
    conv_kv    <<<dim3(48,2),  128, CWAM_SMEM>>>(x);
    qkv_kernel <<<dim3(32,2),  256>>>(x, P);
    cam_kernel <<<dim3(2,8),   256>>>();
    pam_kernel <<<dim3(128,2), 256>>>();
    cham_kernel<<<dim3(64,2),  256>>>();
    cwam_mma   <<<dim3(96,2,3), 128, CWAM_SMEM>>>(x);
    cwam_merge <<<dim3(1536,2), 256>>>();
    epi_kernel <<<dim3(96,2),  256>>>(out, E);
}

// round 16
// speedup vs baseline: 1.2935x; 1.2935x over previous
#include <cuda_runtime.h>
#include <cuda_bf16.h>
#include <math.h>
#include <stdint.h>

#define NTOK 4096
#define NELEM (NTOK*96)
#define SCALE_F 0.35355339059327373f
#define NEG_INF (-3.402823466e38f)

__device__ float g_qkv[9][2][8*NTOK];
__device__ float g_ycam[2][8*NTOK];
__device__ float g_ypam[2][8*NTOK];
__device__ float g_ycham[2][8*NTOK];
__device__ float g_ycwam[2][NELEM];
// split-K3 partials for cwam
__device__ float g_pl[3][2][6144];
__device__ float g_pY[3][2][6144][64];

struct QKVParams { const float* w[9]; const float* bia[9]; };
struct EpiParams { const float* pw[4]; const float* g[4]; const float* gamma[4]; };

// ---- fast exp on the FMA pipe (no MUFU) ----
__device__ __forceinline__ float fexp(float x) {
    x = fmaxf(x, -80.f);
    float t = fmaf(x, 1.4426950408889634f, 12582912.f);
    float e = t - 12582912.f;
    float f = fmaf(x, 1.4426950408889634f, -e);
    float p = 1.5403530e-4f;
    p = fmaf(p, f, 1.3333558e-3f);
    p = fmaf(p, f, 9.6181291e-3f);
    p = fmaf(p, f, 5.5504109e-2f);
    p = fmaf(p, f, 2.4022651e-1f);
    p = fmaf(p, f, 6.9314718e-1f);
    p = fmaf(p, f, 1.0f);
    return p * __int_as_float(((int)e + 127) << 23);
}

// ---- cheap bf16 hi/lo split ----
__device__ __forceinline__ float trunchi(float a) {
    return __int_as_float(__float_as_int(a) & 0xffff0000u);
}
__device__ __forceinline__ uint32_t prmthi(float a, float b) {
    uint32_t r;
    asm("prmt.b32 %0, %1, %2, 0x7632;" : "=r"(r) : "r"(__float_as_int(a)), "r"(__float_as_int(b)));
    return r;
}
__device__ __forceinline__ uint32_t cvt2(float lo, float hi) {
    uint32_t r;
    asm("cvt.rn.bf16x2.f32 %0, %1, %2;" : "=r"(r) : "f"(hi), "f"(lo));
    return r;
}

#define MMA16(d, a, b0, b1) asm volatile( \
    "mma.sync.aligned.m16n8k16.row.col.f32.bf16.bf16.f32 " \
    "{%0,%1,%2,%3},{%4,%5,%6,%7},{%8,%9},{%0,%1,%2,%3};" \
    : "+f"((d)[0]),"+f"((d)[1]),"+f"((d)[2]),"+f"((d)[3]) \
    : "r"((a)[0]),"r"((a)[1]),"r"((a)[2]),"r"((a)[3]), "r"(b0),"r"(b1))

// smem layout in u32 units
#define KHI_O   0            /* 128 tok * 36 u32 */
#define KLO_O   4608
#define VTH_O   9216         /* 64 tokpair * 73 u32 (padded) */
#define VTL_O   13888
#define CWAM_SMEM (18560*4)  /* 74240 B */

// ======== CWAM split-K3 flash (no-max softmax): 6144x6144, d=64 ========
__global__ void __launch_bounds__(128) cwam_mma(const float* __restrict__ x) {
    extern __shared__ uint32_t sm[];
    uint32_t* khi = sm + KHI_O;
    uint32_t* klo = sm + KLO_O;
    uint32_t* vth = sm + VTH_O;
    uint32_t* vtl = sm + VTL_O;
    const int b = blockIdx.y, z = blockIdx.z, a0 = blockIdx.x*64, t = threadIdx.x;
    const int w = t >> 5, lane = t & 31, g = lane >> 2, q = lane & 3;
    const float* xb = x + b*NELEM;
    uint32_t qhi[4][4], qlo[4][4];
    const int r0 = a0 + w*16 + g;
#pragma unroll
    for (int ks = 0; ks < 4; ks++)
#pragma unroll
        for (int half = 0; half < 2; half++)
#pragma unroll
            for (int rr = 0; rr < 2; rr++) {
                int row = r0 + rr*8;
                int col = ks*16 + half*8 + 2*q;
                float2 v = *(const float2*)(xb + row*64 + col);
                v.x *= SCALE_F; v.y *= SCALE_F;
                qhi[ks][half*2+rr] = prmthi(v.x, v.y);
                qlo[ks][half*2+rr] = cvt2(v.x - trunchi(v.x), v.y - trunchi(v.y));
            }
    float l0 = 0.f, l1 = 0.f;
    float Y[8][4];
#pragma unroll
    for (int i = 0; i < 8; i++) { Y[i][0]=0.f; Y[i][1]=0.f; Y[i][2]=0.f; Y[i][3]=0.f; }

    const int cbeg = z*2048, cend = cbeg + 2048;
    for (int c0 = cbeg; c0 < cend; c0 += 128) {
        __syncthreads();
#pragma unroll
        for (int i = 0; i < 8; i++) {
            int j = i*128 + t;
            int tp = j >> 4, dq = j & 15;
            float4 a4 = __ldg((const float4*)(xb + (c0 + 2*tp)*64) + dq);
            float4 b4 = __ldg((const float4*)(xb + (c0 + 2*tp + 1)*64) + dq);
            float rax = a4.x - trunchi(a4.x), ray = a4.y - trunchi(a4.y);
            float raz = a4.z - trunchi(a4.z), raw = a4.w - trunchi(a4.w);
            float rbx = b4.x - trunchi(b4.x), rby = b4.y - trunchi(b4.y);
            float rbz = b4.z - trunchi(b4.z), rbw = b4.w - trunchi(b4.w);
            int ke = (2*tp)*36 + dq*2, ko = ke + 36;
            khi[ke  ] = prmthi(a4.x, a4.y);  khi[ke+1] = prmthi(a4.z, a4.w);
            khi[ko  ] = prmthi(b4.x, b4.y);  khi[ko+1] = prmthi(b4.z, b4.w);
            klo[ke  ] = cvt2(rax, ray);      klo[ke+1] = cvt2(raz, raw);
            klo[ko  ] = cvt2(rbx, rby);      klo[ko+1] = cvt2(rbz, rbw);
            int vb = tp*73 + dq*4;
            vth[vb  ] = prmthi(a4.x, b4.x);
            vth[vb+1] = prmthi(a4.y, b4.y);
            vth[vb+2] = prmthi(a4.z, b4.z);
            vth[vb+3] = prmthi(a4.w, b4.w);
            vtl[vb  ] = cvt2(rax, rbx);
            vtl[vb+1] = cvt2(ray, rby);
            vtl[vb+2] = cvt2(raz, rbz);
            vtl[vb+3] = cvt2(raw, rbw);
        }
        __syncthreads();
        float d[16][4];
#pragma unroll
        for (int ns = 0; ns < 16; ns++) { d[ns][0]=0.f; d[ns][1]=0.f; d[ns][2]=0.f; d[ns][3]=0.f; }
#pragma unroll
        for (int ks = 0; ks < 4; ks++)
#pragma unroll
            for (int ns = 0; ns < 16; ns++) {
                int tok = ns*8 + g;
                uint32_t bh0 = khi[tok*36 + ks*8 + q];
                uint32_t bh1 = khi[tok*36 + ks*8 + 4 + q];
                uint32_t bl0 = klo[tok*36 + ks*8 + q];
                uint32_t bl1 = klo[tok*36 + ks*8 + 4 + q];
                MMA16(d[ns], qhi[ks], bh0, bh1);
                MMA16(d[ns], qhi[ks], bl0, bl1);
                MMA16(d[ns], qlo[ks], bh0, bh1);
            }
#pragma unroll
        for (int ns = 0; ns < 16; ns++) {
            d[ns][0] = fexp(d[ns][0]); d[ns][1] = fexp(d[ns][1]);
            d[ns][2] = fexp(d[ns][2]); d[ns][3] = fexp(d[ns][3]);
            l0 += d[ns][0] + d[ns][1];
            l1 += d[ns][2] + d[ns][3];
        }
#pragma unroll
        for (int ks2 = 0; ks2 < 8; ks2++) {
            uint32_t ah[4], al[4];
            float p00 = d[2*ks2][0],   p01 = d[2*ks2][1];
            float p02 = d[2*ks2][2],   p03 = d[2*ks2][3];
            float p10 = d[2*ks2+1][0], p11 = d[2*ks2+1][1];
            float p12 = d[2*ks2+1][2], p13 = d[2*ks2+1][3];
            ah[0] = prmthi(p00, p01);  al[0] = cvt2(p00 - trunchi(p00), p01 - trunchi(p01));
            ah[1] = prmthi(p02, p03);  al[1] = cvt2(p02 - trunchi(p02), p03 - trunchi(p03));
            ah[2] = prmthi(p10, p11);  al[2] = cvt2(p10 - trunchi(p10), p11 - trunchi(p11));
            ah[3] = prmthi(p12, p13);  al[3] = cvt2(p12 - trunchi(p12), p13 - trunchi(p13));
#pragma unroll
            for (int nd = 0; nd < 8; nd++) {
                int dim = nd*8 + g;
                uint32_t bh0 = vth[(ks2*8 + q)*73 + dim];
                uint32_t bh1 = vth[(ks2*8 + 4 + q)*73 + dim];
                uint32_t bl0 = vtl[(ks2*8 + q)*73 + dim];
                uint32_t bl1 = vtl[(ks2*8 + 4 + q)*73 + dim];
                MMA16(Y[nd], ah, bh0, bh1);
                MMA16(Y[nd], al, bh0, bh1);
                MMA16(Y[nd], ah, bl0, bl1);
            }
        }
    }
#pragma unroll
    for (int off = 1; off <= 2; off <<= 1) {
        l0 += __shfl_xor_sync(0xffffffffu, l0, off);
        l1 += __shfl_xor_sync(0xffffffffu, l1, off);
    }
    float (*pY)[64] = g_pY[z][b];
#pragma unroll
    for (int nd = 0; nd < 8; nd++) {
        int col = nd*8 + 2*q;
        *(float2*)(&pY[r0][col])     = make_float2(Y[nd][0], Y[nd][1]);
        *(float2*)(&pY[r0 + 8][col]) = make_float2(Y[nd][2], Y[nd][3]);
    }
    if (q == 0) {
        g_pl[z][b][r0]   = l0;
        g_pl[z][b][r0+8] = l1;
    }
}

// merge: Y = sum(Yz) / sum(lz)
__global__ void __launch_bounds__(256) cwam_merge() {
    const int b = blockIdx.y;
    const int row = blockIdx.x*4 + (threadIdx.x >> 6);
    const int d = threadIdx.x & 63;
    float l = g_pl[0][b][row] + g_pl[1][b][row] + g_pl[2][b][row];
    float y = g_pY[0][b][row][d] + g_pY[1][b][row][d] + g_pY[2][b][row][d];
    g_ycwam[b][row*64 + d] = y / l;
}

// ======== fused qkv conv1x1 ========
__global__ void __launch_bounds__(256) qkv_kernel(const float* __restrict__ x, QKVParams P) {
    __shared__ float sw[72*100];
    __shared__ float sb[72];
    const int b = blockIdx.y, n0 = blockIdx.x*128, t = threadIdx.x;
    for (int i = t; i < 72*96; i += 256) {
        int o = i/96, c = i - o*96;
        sw[o*100+c] = __ldg(P.w[o%9] + (o/9)*96 + c);
    }
    if (t < 72) sb[t] = __ldg(P.bia[t%9] + t/9);
    __syncthreads();
    const int og = t & 7, nl = t >> 3;
    const float* xb = x + b*NELEM + n0 + nl;
    float acc[9][4];
#pragma unroll
    for (int kk = 0; kk < 9; kk++) {
        float bb = sb[og*9+kk];
#pragma unroll
        for (int j = 0; j < 4; j++) acc[kk][j] = bb;
    }
    for (int c = 0; c < 96; c++) {
        float xv[4];
#pragma unroll
        for (int j = 0; j < 4; j++) xv[j] = __ldg(xb + c*NTOK + 32*j);
#pragma unroll
        for (int kk = 0; kk < 9; kk++) {
            float wv = sw[(og*9+kk)*100 + c];
#pragma unroll
            for (int j = 0; j < 4; j++) acc[kk][j] += wv*xv[j];
        }
    }
#pragma unroll
    for (int kk = 0; kk < 9; kk++)
#pragma unroll
        for (int j = 0; j < 4; j++)
            g_qkv[kk][b][og*NTOK + n0 + nl + 32*j] = acc[kk][j];
}

// ======== CAM ========
__global__ void __launch_bounds__(256) cam_kernel() {
    const int b = blockIdx.x, slice = blockIdx.y;
    const float *q = g_qkv[0][b], *k = g_qkv[1][b], *v = g_qkv[2][b];
    __shared__ float sp[8][8];
    const int w = threadIdx.x >> 5, lane = threadIdx.x & 31;
    float acc[8] = {};
    for (int i = lane; i < NTOK; i += 32) {
        float qv = q[w*NTOK+i];
#pragma unroll
        for (int d = 0; d < 8; d++) acc[d] += qv*k[d*NTOK+i];
    }
#pragma unroll
    for (int d = 0; d < 8; d++)
#pragma unroll
        for (int off = 16; off; off >>= 1)
            acc[d] += __shfl_xor_sync(0xffffffffu, acc[d], off);
    if (lane == 0) {
        float mx = NEG_INF, s = 0.f, e[8];
#pragma unroll
        for (int d = 0; d < 8; d++) mx = fmaxf(mx, acc[d]*SCALE_F);
#pragma unroll
        for (int d = 0; d < 8; d++) { e[d] = fexp(acc[d]*SCALE_F - mx); s += e[d]; }
#pragma unroll
        for (int d = 0; d < 8; d++) sp[w][d] = e[d]/s;
    }
    __syncthreads();
    for (int idx = threadIdx.x; idx < 4096; idx += 256) {
        int c = idx >> 9, n = slice*512 + (idx & 511);
        float a0 = 0.f;
#pragma unroll
        for (int d = 0; d < 8; d++) a0 += sp[c][d]*v[d*NTOK+n];
        g_ycam[b][c*NTOK+n] = a0;
    }
}

// ======== PAM v4: 2 rows/thread, 16-way m-split, conflict-free padded smem ========
// grid (128,2): CTA covers 32 rows (thread t: rows a0 + (t>>4) and a0 + (t>>4) + 16)
__global__ void __launch_bounds__(256) pam_kernel() {
    const int a0 = blockIdx.x*32, b = blockIdx.y;
    const float *q = g_qkv[3][b], *k = g_qkv[4][b], *v = g_qkv[5][b];
    __shared__ float kt[512][12], vt[512][12];   // 48B rows: conflict-free LDS.128
    const int t = threadIdx.x, a = t >> 4, p = t & 15;
    float qr0[8], qr1[8];
#pragma unroll
    for (int c = 0; c < 8; c++) {
        qr0[c] = q[c*NTOK + a0 + a]*SCALE_F;
        qr1[c] = q[c*NTOK + a0 + a + 16]*SCALE_F;
    }
    float l0 = 0.f, l1 = 0.f, y0[8] = {}, y1[8] = {};
    for (int m0 = 0; m0 < NTOK; m0 += 512) {
        __syncthreads();
        for (int i = t; i < 4096; i += 256) {
            int c = i >> 9, mm = i & 511;
            kt[mm][c] = k[c*NTOK + m0 + mm];
            vt[mm][c] = v[c*NTOK + m0 + mm];
        }
        __syncthreads();
        for (int mi = p; mi < 512; mi += 16) {
            float4 k0 = *(const float4*)&kt[mi][0], k1 = *(const float4*)&kt[mi][4];
            float s0 = qr0[0]*k0.x+qr0[1]*k0.y+qr0[2]*k0.z+qr0[3]*k0.w
                     + qr0[4]*k1.x+qr0[5]*k1.y+qr0[6]*k1.z+qr0[7]*k1.w;
            float s1 = qr1[0]*k0.x+qr1[1]*k0.y+qr1[2]*k0.z+qr1[3]*k0.w
                     + qr1[4]*k1.x+qr1[5]*k1.y+qr1[6]*k1.z+qr1[7]*k1.w;
            float pe0 = fexp(s0), pe1 = fexp(s1);
            l0 += pe0; l1 += pe1;
            float4 v0 = *(const float4*)&vt[mi][0], v1 = *(const float4*)&vt[mi][4];
            y0[0]+=pe0*v0.x; y0[1]+=pe0*v0.y; y0[2]+=pe0*v0.z; y0[3]+=pe0*v0.w;
            y0[4]+=pe0*v1.x; y0[5]+=pe0*v1.y; y0[6]+=pe0*v1.z; y0[7]+=pe0*v1.w;
            y1[0]+=pe1*v0.x; y1[1]+=pe1*v0.y; y1[2]+=pe1*v0.z; y1[3]+=pe1*v0.w;
            y1[4]+=pe1*v1.x; y1[5]+=pe1*v1.y; y1[6]+=pe1*v1.z; y1[7]+=pe1*v1.w;
        }
    }
    // merge the 16 p-partials (within each 16-lane half-warp)
#pragma unroll
    for (int off = 1; off <= 8; off <<= 1) {
        l0 += __shfl_xor_sync(0xffffffffu, l0, off);
        l1 += __shfl_xor_sync(0xffffffffu, l1, off);
#pragma unroll
        for (int c = 0; c < 8; c++) {
            y0[c] += __shfl_xor_sync(0xffffffffu, y0[c], off);
            y1[c] += __shfl_xor_sync(0xffffffffu, y1[c], off);
        }
    }
    if (p == 0) {
        float i0 = 1.f/l0, i1 = 1.f/l1;
#pragma unroll
        for (int c = 0; c < 8; c++) {
            g_ypam[b][(a0 + a)*8 + c]      = y0[c]*i0;
            g_ypam[b][(a0 + a + 16)*8 + c] = y1[c]*i1;
        }
    }
}

// ======== CHAM v3: 512x512, d=64; 8 rows/CTA, smem-staged tiles ========
__global__ void __launch_bounds__(256) cham_kernel() {
    const int a0 = blockIdx.x*8, b = blockIdx.y;
    const float *q = g_qkv[6][b], *k = g_qkv[7][b], *v = g_qkv[8][b];
    __shared__ float sq[8][68];
    __shared__ float kt[64][68];
    __shared__ float ss[8][520];
    const int t = threadIdx.x, r = t >> 5, ln = t & 31;
    for (int i = t; i < 512; i += 256)
        sq[i>>6][i&63] = q[(a0 + (i>>6))*64 + (i&63)] * SCALE_F;
    for (int ch = 0; ch < 8; ch++) {
        __syncthreads();
        for (int i = 0; i < 16; i++) {
            int idx = i*256 + t;
            kt[idx>>6][idx&63] = __ldg(k + ch*4096 + idx);
        }
        __syncthreads();
        float s0 = 0.f, s1 = 0.f;
#pragma unroll
        for (int i = 0; i < 16; i++) {
            float4 qv = *(const float4*)&sq[r][i*4];
            float4 k0 = *(const float4*)&kt[ln][i*4];
            float4 k1 = *(const float4*)&kt[ln+32][i*4];
            s0 += qv.x*k0.x + qv.y*k0.y + qv.z*k0.z + qv.w*k0.w;
            s1 += qv.x*k1.x + qv.y*k1.y + qv.z*k1.z + qv.w*k1.w;
        }
        ss[r][ch*64 + ln]      = s0;
        ss[r][ch*64 + ln + 32] = s1;
    }
    __syncthreads();
    float vals[16], M = NEG_INF;
#pragma unroll
    for (int j = 0; j < 16; j++) { vals[j] = ss[r][ln + 32*j]; M = fmaxf(M, vals[j]); }
#pragma unroll
    for (int off = 16; off; off >>= 1) M = fmaxf(M, __shfl_xor_sync(0xffffffffu, M, off));
    float S = 0.f;
#pragma unroll
    for (int j = 0; j < 16; j++) { vals[j] = fexp(vals[j] - M); S += vals[j]; }
#pragma unroll
    for (int off = 16; off; off >>= 1) S += __shfl_xor_sync(0xffffffffu, S, off);
    float inv = 1.f / S;
#pragma unroll
    for (int j = 0; j < 16; j++) ss[r][ln + 32*j] = vals[j] * inv;
    float y0 = 0.f, y1 = 0.f;
    for (int ch = 0; ch < 8; ch++) {
        __syncthreads();
        for (int i = 0; i < 16; i++) {
            int idx = i*256 + t;
            kt[idx>>6][idx&63] = __ldg(v + ch*4096 + idx);
        }
        __syncthreads();
#pragma unroll 8
        for (int c = 0; c < 64; c++) {
            float pv = ss[r][ch*64 + c];
            y0 += pv * kt[c][ln];
            y1 += pv * kt[c][ln+32];
        }
    }
    g_ycham[b][(a0+r)*64 + ln]      = y0;
    g_ycham[b][(a0+r)*64 + ln + 32] = y1;
}

// ======== epilogue ========
__global__ void __launch_bounds__(256) epi_kernel(float* __restrict__ out, EpiParams E) {
    const int b = blockIdx.y, o = blockIdx.x;
    __shared__ float w[4][9];
    __shared__ float gg[4];
    if (threadIdx.x < 36)
        w[threadIdx.x/9][threadIdx.x%9] = __ldg(E.pw[threadIdx.x/9] + o*9 + threadIdx.x%9);
    if (threadIdx.x < 4)
        gg[threadIdx.x] = __ldg(E.gamma[threadIdx.x]) * (1.f + __ldg(E.g[threadIdx.x]));
    __syncthreads();
    const int g8 = o/12;
    const float* inp[4] = { g_ycam[b] + g8*4096, g_ypam[b] + g8*4096,
                            g_ycham[b] + g8*4096, g_ycwam[b] + o*4096 };
    for (int pix = threadIdx.x; pix < 4096; pix += 256) {
        int h = pix >> 6, wx = pix & 63;
        float acc = 0.f;
#pragma unroll
        for (int br = 0; br < 4; br++) {
            float c = 0.f;
#pragma unroll
            for (int dy = -1; dy <= 1; dy++)
#pragma unroll
                for (int dx = -1; dx <= 1; dx++) {
                    int hh2 = h + dy, ww = wx + dx;
                    float vv = (hh2 >= 0 && hh2 < 64 && ww >= 0 && ww < 64)
                               ? __ldg(inp[br] + hh2*64 + ww) : 0.f;
                    c += w[br][(dy+1)*3 + dx + 1] * vv;
                }
            float ge = 0.5f*c*(1.f + erff(c*0.70710678118654752f));
            acc += gg[br]*ge;
        }
        out[b*NELEM + pix*96 + o] = acc;
    }
}

extern "C" void kernel_launch(void* const* d_in, const int* in_sizes, int n_in,
                              void* d_out, int out_size) {
    const float* x = (const float*)d_in[0];
    static const int wi[9] = {1,3,5, 9,11,13, 17,19,21};
    QKVParams P;
    for (int i = 0; i < 9; i++) {
        P.w[i]   = (const float*)d_in[wi[i]];
        P.bia[i] = (const float*)d_in[wi[i]+1];
    }
    static const int pi[4] = {7,15,23,25};
    EpiParams E;
    for (int i = 0; i < 4; i++) {
        E.pw[i]    = (const float*)d_in[pi[i]];
        E.g[i]     = (const float*)d_in[pi[i]+1];
        E.gamma[i] = (const float*)d_in[27+i];
    }
    float* out = (float*)d_out;
    cudaFuncSetAttribute(cwam_mma, cudaFuncAttributeMaxDynamicSharedMemorySize, CWAM_SMEM);
    qkv_kernel <<<dim3(32,2),  256>>>(x, P);
    cam_kernel <<<dim3(2,8),   256>>>();
    pam_kernel <<<dim3(128,2), 256>>>();
    cham_kernel<<<dim3(64,2),  256>>>();
    cwam_mma   <<<dim3(96,2,3), 128, CWAM_SMEM>>>(x);
    cwam_merge <<<dim3(1536,2), 256>>>();
    epi_kernel <<<dim3(96,2),  256>>>(out, E);
}

// round 17
// speedup vs baseline: 1.5709x; 1.2144x over previous
#include <cuda_runtime.h>
#include <cuda_bf16.h>
#include <math.h>
#include <stdint.h>

#define NTOK 4096
#define NELEM (NTOK*96)
#define SCALE_L2 0.51008664090843785f   /* (C/12)^-0.5 * log2(e) */
#define NEG_INF (-3.402823466e38f)

__device__ float g_qkv[9][2][8*NTOK];
__device__ float g_ycam[2][8*NTOK];
__device__ float g_ypam[2][8*NTOK];
__device__ float g_ycham[2][8*NTOK];
__device__ float g_ycwam[2][NELEM];
__device__ float g_pl[3][2][6144];
__device__ float g_pY[3][2][6144][64];

struct QKVParams { const float* w[9]; const float* bia[9]; };
struct EpiParams { const float* pw[4]; const float* g[4]; const float* gamma[4]; };

// ---- fast exp2 on the FMA pipe (input already in log2 units) ----
__device__ __forceinline__ float fexp2(float x) {
    x = fmaxf(x, -120.f);
    float t = x + 12582912.f;
    float e = t - 12582912.f;
    float f = x - e;                      // [-0.5, 0.5]
    float p = 1.5403530e-4f;
    p = fmaf(p, f, 1.3333558e-3f);
    p = fmaf(p, f, 9.6181291e-3f);
    p = fmaf(p, f, 5.5504109e-2f);
    p = fmaf(p, f, 2.4022651e-1f);
    p = fmaf(p, f, 6.9314718e-1f);
    p = fmaf(p, f, 1.0f);
    return p * __int_as_float(((int)e + 127) << 23);
}

// ---- cheap bf16 hi/lo split ----
__device__ __forceinline__ float trunchi(float a) {
    return __int_as_float(__float_as_int(a) & 0xffff0000u);
}
__device__ __forceinline__ uint32_t prmthi(float a, float b) {
    uint32_t r;
    asm("prmt.b32 %0, %1, %2, 0x7632;" : "=r"(r) : "r"(__float_as_int(a)), "r"(__float_as_int(b)));
    return r;
}
__device__ __forceinline__ uint32_t cvt2(float lo, float hi) {
    uint32_t r;
    asm("cvt.rn.bf16x2.f32 %0, %1, %2;" : "=r"(r) : "f"(hi), "f"(lo));
    return r;
}

#define MMA16(d, a, b0, b1) asm volatile( \
    "mma.sync.aligned.m16n8k16.row.col.f32.bf16.bf16.f32 " \
    "{%0,%1,%2,%3},{%4,%5,%6,%7},{%8,%9},{%0,%1,%2,%3};" \
    : "+f"((d)[0]),"+f"((d)[1]),"+f"((d)[2]),"+f"((d)[3]) \
    : "r"((a)[0]),"r"((a)[1]),"r"((a)[2]),"r"((a)[3]), "r"(b0),"r"(b1))

#define KHI_O   0
#define KLO_O   4608
#define VTH_O   9216
#define VTL_O   13888
#define CWAM_SMEM (18560*4)

// ======== CWAM split-K3 flash (exp2 no-max softmax): 6144x6144, d=64 ========
__global__ void __launch_bounds__(128) cwam_mma(const float* __restrict__ x) {
    extern __shared__ uint32_t sm[];
    uint32_t* khi = sm + KHI_O;
    uint32_t* klo = sm + KLO_O;
    uint32_t* vth = sm + VTH_O;
    uint32_t* vtl = sm + VTL_O;
    const int b = blockIdx.y, z = blockIdx.z, a0 = blockIdx.x*64, t = threadIdx.x;
    const int w = t >> 5, lane = t & 31, g = lane >> 2, q = lane & 3;
    const float* xb = x + b*NELEM;
    uint32_t qhi[4][4], qlo[4][4];
    const int r0 = a0 + w*16 + g;
#pragma unroll
    for (int ks = 0; ks < 4; ks++)
#pragma unroll
        for (int half = 0; half < 2; half++)
#pragma unroll
            for (int rr = 0; rr < 2; rr++) {
                int row = r0 + rr*8;
                int col = ks*16 + half*8 + 2*q;
                float2 v = *(const float2*)(xb + row*64 + col);
                v.x *= SCALE_L2; v.y *= SCALE_L2;
                qhi[ks][half*2+rr] = prmthi(v.x, v.y);
                qlo[ks][half*2+rr] = cvt2(v.x - trunchi(v.x), v.y - trunchi(v.y));
            }
    float l0 = 0.f, l1 = 0.f;
    float Y[8][4];
#pragma unroll
    for (int i = 0; i < 8; i++) { Y[i][0]=0.f; Y[i][1]=0.f; Y[i][2]=0.f; Y[i][3]=0.f; }

    const int cbeg = z*2048, cend = cbeg + 2048;
    for (int c0 = cbeg; c0 < cend; c0 += 128) {
        __syncthreads();
#pragma unroll
        for (int i = 0; i < 8; i++) {
            int j = i*128 + t;
            int tp = j >> 4, dq = j & 15;
            float4 a4 = __ldg((const float4*)(xb + (c0 + 2*tp)*64) + dq);
            float4 b4 = __ldg((const float4*)(xb + (c0 + 2*tp + 1)*64) + dq);
            float rax = a4.x - trunchi(a4.x), ray = a4.y - trunchi(a4.y);
            float raz = a4.z - trunchi(a4.z), raw = a4.w - trunchi(a4.w);
            float rbx = b4.x - trunchi(b4.x), rby = b4.y - trunchi(b4.y);
            float rbz = b4.z - trunchi(b4.z), rbw = b4.w - trunchi(b4.w);
            int ke = (2*tp)*36 + dq*2, ko = ke + 36;
            khi[ke  ] = prmthi(a4.x, a4.y);  khi[ke+1] = prmthi(a4.z, a4.w);
            khi[ko  ] = prmthi(b4.x, b4.y);  khi[ko+1] = prmthi(b4.z, b4.w);
            klo[ke  ] = cvt2(rax, ray);      klo[ke+1] = cvt2(raz, raw);
            klo[ko  ] = cvt2(rbx, rby);      klo[ko+1] = cvt2(rbz, rbw);
            int vb = tp*73 + dq*4;
            vth[vb  ] = prmthi(a4.x, b4.x);
            vth[vb+1] = prmthi(a4.y, b4.y);
            vth[vb+2] = prmthi(a4.z, b4.z);
            vth[vb+3] = prmthi(a4.w, b4.w);
            vtl[vb  ] = cvt2(rax, rbx);
            vtl[vb+1] = cvt2(ray, rby);
            vtl[vb+2] = cvt2(raz, rbz);
            vtl[vb+3] = cvt2(raw, rbw);
        }
        __syncthreads();
        float d[16][4];
#pragma unroll
        for (int ns = 0; ns < 16; ns++) { d[ns][0]=0.f; d[ns][1]=0.f; d[ns][2]=0.f; d[ns][3]=0.f; }
#pragma unroll
        for (int ks = 0; ks < 4; ks++)
#pragma unroll
            for (int ns = 0; ns < 16; ns++) {
                int tok = ns*8 + g;
                uint32_t bh0 = khi[tok*36 + ks*8 + q];
                uint32_t bh1 = khi[tok*36 + ks*8 + 4 + q];
                uint32_t bl0 = klo[tok*36 + ks*8 + q];
                uint32_t bl1 = klo[tok*36 + ks*8 + 4 + q];
                MMA16(d[ns], qhi[ks], bh0, bh1);
                MMA16(d[ns], qhi[ks], bl0, bl1);
                MMA16(d[ns], qlo[ks], bh0, bh1);
            }
#pragma unroll
        for (int ns = 0; ns < 16; ns++) {
            d[ns][0] = fexp2(d[ns][0]); d[ns][1] = fexp2(d[ns][1]);
            d[ns][2] = fexp2(d[ns][2]); d[ns][3] = fexp2(d[ns][3]);
            l0 += d[ns][0] + d[ns][1];
            l1 += d[ns][2] + d[ns][3];
        }
#pragma unroll
        for (int ks2 = 0; ks2 < 8; ks2++) {
            uint32_t ah[4], al[4];
            float p00 = d[2*ks2][0],   p01 = d[2*ks2][1];
            float p02 = d[2*ks2][2],   p03 = d[2*ks2][3];
            float p10 = d[2*ks2+1][0], p11 = d[2*ks2+1][1];
            float p12 = d[2*ks2+1][2], p13 = d[2*ks2+1][3];
            ah[0] = prmthi(p00, p01);  al[0] = cvt2(p00 - trunchi(p00), p01 - trunchi(p01));
            ah[1] = prmthi(p02, p03);  al[1] = cvt2(p02 - trunchi(p02), p03 - trunchi(p03));
            ah[2] = prmthi(p10, p11);  al[2] = cvt2(p10 - trunchi(p10), p11 - trunchi(p11));
            ah[3] = prmthi(p12, p13);  al[3] = cvt2(p12 - trunchi(p12), p13 - trunchi(p13));
#pragma unroll
            for (int nd = 0; nd < 8; nd++) {
                int dim = nd*8 + g;
                uint32_t bh0 = vth[(ks2*8 + q)*73 + dim];
                uint32_t bh1 = vth[(ks2*8 + 4 + q)*73 + dim];
                uint32_t bl0 = vtl[(ks2*8 + q)*73 + dim];
                uint32_t bl1 = vtl[(ks2*8 + 4 + q)*73 + dim];
                MMA16(Y[nd], ah, bh0, bh1);
                MMA16(Y[nd], al, bh0, bh1);
                MMA16(Y[nd], ah, bl0, bl1);
            }
        }
    }
#pragma unroll
    for (int off = 1; off <= 2; off <<= 1) {
        l0 += __shfl_xor_sync(0xffffffffu, l0, off);
        l1 += __shfl_xor_sync(0xffffffffu, l1, off);
    }
    float (*pY)[64] = g_pY[z][b];
#pragma unroll
    for (int nd = 0; nd < 8; nd++) {
        int col = nd*8 + 2*q;
        *(float2*)(&pY[r0][col])     = make_float2(Y[nd][0], Y[nd][1]);
        *(float2*)(&pY[r0 + 8][col]) = make_float2(Y[nd][2], Y[nd][3]);
    }
    if (q == 0) {
        g_pl[z][b][r0]   = l0;
        g_pl[z][b][r0+8] = l1;
    }
}

__global__ void __launch_bounds__(256) cwam_merge() {
    const int b = blockIdx.y;
    const int row = blockIdx.x*4 + (threadIdx.x >> 6);
    const int d = threadIdx.x & 63;
    float l = g_pl[0][b][row] + g_pl[1][b][row] + g_pl[2][b][row];
    float y = g_pY[0][b][row][d] + g_pY[1][b][row][d] + g_pY[2][b][row][d];
    g_ycwam[b][row*64 + d] = y / l;
}

// ======== fused qkv conv1x1 ========
__global__ void __launch_bounds__(256) qkv_kernel(const float* __restrict__ x, QKVParams P) {
    __shared__ float sw[72*100];
    __shared__ float sb[72];
    const int b = blockIdx.y, n0 = blockIdx.x*128, t = threadIdx.x;
    for (int i = t; i < 72*96; i += 256) {
        int o = i/96, c = i - o*96;
        sw[o*100+c] = __ldg(P.w[o%9] + (o/9)*96 + c);
    }
    if (t < 72) sb[t] = __ldg(P.bia[t%9] + t/9);
    __syncthreads();
    const int og = t & 7, nl = t >> 3;
    const float* xb = x + b*NELEM + n0 + nl;
    float acc[9][4];
#pragma unroll
    for (int kk = 0; kk < 9; kk++) {
        float bb = sb[og*9+kk];
#pragma unroll
        for (int j = 0; j < 4; j++) acc[kk][j] = bb;
    }
    for (int c = 0; c < 96; c++) {
        float xv[4];
#pragma unroll
        for (int j = 0; j < 4; j++) xv[j] = __ldg(xb + c*NTOK + 32*j);
#pragma unroll
        for (int kk = 0; kk < 9; kk++) {
            float wv = sw[(og*9+kk)*100 + c];
#pragma unroll
            for (int j = 0; j < 4; j++) acc[kk][j] += wv*xv[j];
        }
    }
#pragma unroll
    for (int kk = 0; kk < 9; kk++)
#pragma unroll
        for (int j = 0; j < 4; j++)
            g_qkv[kk][b][og*NTOK + n0 + nl + 32*j] = acc[kk][j];
}

// ======== fused mid kernel: pam (bx<128) | cham (128<=bx<192) | cam (bx>=192) ====
__device__ void pam_body(int ax, int b, float* smem) {
    const float *q = g_qkv[3][b], *k = g_qkv[4][b], *v = g_qkv[5][b];
    float (*kt)[12] = (float(*)[12])smem;
    float (*vt)[12] = (float(*)[12])(smem + 6144);
    const int a0 = ax*32, t = threadIdx.x, a = t >> 4, p = t & 15;
    float qr0[8], qr1[8];
#pragma unroll
    for (int c = 0; c < 8; c++) {
        qr0[c] = q[c*NTOK + a0 + a]*SCALE_L2;
        qr1[c] = q[c*NTOK + a0 + a + 16]*SCALE_L2;
    }
    float l0 = 0.f, l1 = 0.f, y0[8] = {}, y1[8] = {};
    for (int m0 = 0; m0 < NTOK; m0 += 512) {
        __syncthreads();
        for (int i = t; i < 4096; i += 256) {
            int c = i >> 9, mm = i & 511;
            kt[mm][c] = k[c*NTOK + m0 + mm];
            vt[mm][c] = v[c*NTOK + m0 + mm];
        }
        __syncthreads();
        for (int mi = p; mi < 512; mi += 16) {
            float4 k0 = *(const float4*)&kt[mi][0], k1 = *(const float4*)&kt[mi][4];
            float s0 = qr0[0]*k0.x+qr0[1]*k0.y+qr0[2]*k0.z+qr0[3]*k0.w
                     + qr0[4]*k1.x+qr0[5]*k1.y+qr0[6]*k1.z+qr0[7]*k1.w;
            float s1 = qr1[0]*k0.x+qr1[1]*k0.y+qr1[2]*k0.z+qr1[3]*k0.w
                     + qr1[4]*k1.x+qr1[5]*k1.y+qr1[6]*k1.z+qr1[7]*k1.w;
            float pe0 = fexp2(s0), pe1 = fexp2(s1);
            l0 += pe0; l1 += pe1;
            float4 v0 = *(const float4*)&vt[mi][0], v1 = *(const float4*)&vt[mi][4];
            y0[0]+=pe0*v0.x; y0[1]+=pe0*v0.y; y0[2]+=pe0*v0.z; y0[3]+=pe0*v0.w;
            y0[4]+=pe0*v1.x; y0[5]+=pe0*v1.y; y0[6]+=pe0*v1.z; y0[7]+=pe0*v1.w;
            y1[0]+=pe1*v0.x; y1[1]+=pe1*v0.y; y1[2]+=pe1*v0.z; y1[3]+=pe1*v0.w;
            y1[4]+=pe1*v1.x; y1[5]+=pe1*v1.y; y1[6]+=pe1*v1.z; y1[7]+=pe1*v1.w;
        }
    }
#pragma unroll
    for (int off = 1; off <= 8; off <<= 1) {
        l0 += __shfl_xor_sync(0xffffffffu, l0, off);
        l1 += __shfl_xor_sync(0xffffffffu, l1, off);
#pragma unroll
        for (int c = 0; c < 8; c++) {
            y0[c] += __shfl_xor_sync(0xffffffffu, y0[c], off);
            y1[c] += __shfl_xor_sync(0xffffffffu, y1[c], off);
        }
    }
    if (p == 0) {
        float i0 = 1.f/l0, i1 = 1.f/l1;
#pragma unroll
        for (int c = 0; c < 8; c++) {
            g_ypam[b][(a0 + a)*8 + c]      = y0[c]*i0;
            g_ypam[b][(a0 + a + 16)*8 + c] = y1[c]*i1;
        }
    }
}

__device__ void cham_body(int cx, int b, float* smem) {
    const float *q = g_qkv[6][b], *k = g_qkv[7][b], *v = g_qkv[8][b];
    float (*sq)[68] = (float(*)[68])smem;               // 544 floats
    float (*kt)[68] = (float(*)[68])(smem + 544);       // 4352
    float (*ss)[520] = (float(*)[520])(smem + 4896);    // 4160
    const int a0 = cx*8, t = threadIdx.x, r = t >> 5, ln = t & 31;
    for (int i = t; i < 512; i += 256)
        sq[i>>6][i&63] = q[(a0 + (i>>6))*64 + (i&63)] * SCALE_L2;
    for (int ch = 0; ch < 8; ch++) {
        __syncthreads();
        for (int i = 0; i < 16; i++) {
            int idx = i*256 + t;
            kt[idx>>6][idx&63] = __ldg(k + ch*4096 + idx);
        }
        __syncthreads();
        float s0 = 0.f, s1 = 0.f;
#pragma unroll
        for (int i = 0; i < 16; i++) {
            float4 qv = *(const float4*)&sq[r][i*4];
            float4 k0 = *(const float4*)&kt[ln][i*4];
            float4 k1 = *(const float4*)&kt[ln+32][i*4];
            s0 += qv.x*k0.x + qv.y*k0.y + qv.z*k0.z + qv.w*k0.w;
            s1 += qv.x*k1.x + qv.y*k1.y + qv.z*k1.z + qv.w*k1.w;
        }
        ss[r][ch*64 + ln]      = s0;
        ss[r][ch*64 + ln + 32] = s1;
    }
    __syncthreads();
    float vals[16], M = NEG_INF;
#pragma unroll
    for (int j = 0; j < 16; j++) { vals[j] = ss[r][ln + 32*j]; M = fmaxf(M, vals[j]); }
#pragma unroll
    for (int off = 16; off; off >>= 1) M = fmaxf(M, __shfl_xor_sync(0xffffffffu, M, off));
    float S = 0.f;
#pragma unroll
    for (int j = 0; j < 16; j++) { vals[j] = fexp2(vals[j] - M); S += vals[j]; }
#pragma unroll
    for (int off = 16; off; off >>= 1) S += __shfl_xor_sync(0xffffffffu, S, off);
    float inv = 1.f / S;
#pragma unroll
    for (int j = 0; j < 16; j++) ss[r][ln + 32*j] = vals[j] * inv;
    float y0 = 0.f, y1 = 0.f;
    for (int ch = 0; ch < 8; ch++) {
        __syncthreads();
        for (int i = 0; i < 16; i++) {
            int idx = i*256 + t;
            kt[idx>>6][idx&63] = __ldg(v + ch*4096 + idx);
        }
        __syncthreads();
#pragma unroll 8
        for (int c = 0; c < 64; c++) {
            float pv = ss[r][ch*64 + c];
            y0 += pv * kt[c][ln];
            y1 += pv * kt[c][ln+32];
        }
    }
    g_ycham[b][(a0+r)*64 + ln]      = y0;
    g_ycham[b][(a0+r)*64 + ln + 32] = y1;
}

__device__ void cam_body(int slice, int b, float* smem) {
    const float *q = g_qkv[0][b], *k = g_qkv[1][b], *v = g_qkv[2][b];
    float (*sp)[8] = (float(*)[8])smem;
    const int w = threadIdx.x >> 5, lane = threadIdx.x & 31;
    float acc[8] = {};
    for (int i = lane; i < NTOK; i += 32) {
        float qv = q[w*NTOK+i];
#pragma unroll
        for (int d = 0; d < 8; d++) acc[d] += qv*k[d*NTOK+i];
    }
#pragma unroll
    for (int d = 0; d < 8; d++)
#pragma unroll
        for (int off = 16; off; off >>= 1)
            acc[d] += __shfl_xor_sync(0xffffffffu, acc[d], off);
    if (lane == 0) {
        float mx = NEG_INF, s = 0.f, e[8];
#pragma unroll
        for (int d = 0; d < 8; d++) mx = fmaxf(mx, acc[d]*SCALE_L2);
#pragma unroll
        for (int d = 0; d < 8; d++) { e[d] = fexp2(acc[d]*SCALE_L2 - mx); s += e[d]; }
#pragma unroll
        for (int d = 0; d < 8; d++) sp[w][d] = e[d]/s;
    }
    __syncthreads();
    for (int idx = threadIdx.x; idx < 4096; idx += 256) {
        int c = idx >> 9, n = slice*512 + (idx & 511);
        float a0 = 0.f;
#pragma unroll
        for (int d = 0; d < 8; d++) a0 += sp[c][d]*v[d*NTOK+n];
        g_ycam[b][c*NTOK+n] = a0;
    }
}

__global__ void __launch_bounds__(256) mid_kernel() {
    __shared__ __align__(16) float smem_u[12288];   // 48 KB union
    const int bx = blockIdx.x, b = blockIdx.y;
    if (bx < 128)      pam_body(bx, b, smem_u);
    else if (bx < 192) cham_body(bx - 128, b, smem_u);
    else               cam_body(bx - 192, b, smem_u);
}

// ======== epilogue ========
__global__ void __launch_bounds__(256) epi_kernel(float* __restrict__ out, EpiParams E) {
    const int b = blockIdx.y, o = blockIdx.x;
    __shared__ float w[4][9];
    __shared__ float gg[4];
    if (threadIdx.x < 36)
        w[threadIdx.x/9][threadIdx.x%9] = __ldg(E.pw[threadIdx.x/9] + o*9 + threadIdx.x%9);
    if (threadIdx.x < 4)
        gg[threadIdx.x] = __ldg(E.gamma[threadIdx.x]) * (1.f + __ldg(E.g[threadIdx.x]));
    __syncthreads();
    const int g8 = o/12;
    const float* inp[4] = { g_ycam[b] + g8*4096, g_ypam[b] + g8*4096,
                            g_ycham[b] + g8*4096, g_ycwam[b] + o*4096 };
    for (int pix = threadIdx.x; pix < 4096; pix += 256) {
        int h = pix >> 6, wx = pix & 63;
        float acc = 0.f;
#pragma unroll
        for (int br = 0; br < 4; br++) {
            float c = 0.f;
#pragma unroll
            for (int dy = -1; dy <= 1; dy++)
#pragma unroll
                for (int dx = -1; dx <= 1; dx++) {
                    int hh2 = h + dy, ww = wx + dx;
                    float vv = (hh2 >= 0 && hh2 < 64 && ww >= 0 && ww < 64)
                               ? __ldg(inp[br] + hh2*64 + ww) : 0.f;
                    c += w[br][(dy+1)*3 + dx + 1] * vv;
                }
            float ge = 0.5f*c*(1.f + erff(c*0.70710678118654752f));
            acc += gg[br]*ge;
        }
        out[b*NELEM + pix*96 + o] = acc;
    }
}

extern "C" void kernel_launch(void* const* d_in, const int* in_sizes, int n_in,
                              void* d_out, int out_size) {
    const float* x = (const float*)d_in[0];
    static const int wi[9] = {1,3,5, 9,11,13, 17,19,21};
    QKVParams P;
    for (int i = 0; i < 9; i++) {
        P.w[i]   = (const float*)d_in[wi[i]];
        P.bia[i] = (const float*)d_in[wi[i]+1];
    }
    static const int pi[4] = {7,15,23,25};
    EpiParams E;
    for (int i = 0; i < 4; i++) {
        E.pw[i]    = (const float*)d_in[pi[i]];
        E.g[i]     = (const float*)d_in[pi[i]+1];
        E.gamma[i] = (const float*)d_in[27+i];
    }
    float* out = (float*)d_out;
    cudaFuncSetAttribute(cwam_mma, cudaFuncAttributeMaxDynamicSharedMemorySize, CWAM_SMEM);
    qkv_kernel <<<dim3(32,2),  256>>>(x, P);
    mid_kernel <<<dim3(200,2), 256>>>();
    cwam_mma   <<<dim3(96,2,3), 128, CWAM_SMEM>>>(x);
    cwam_merge <<<dim3(1536,2), 256>>>();
    epi_kernel <<<dim3(96,2),  256>>>(out, E);
}